// round 1
// baseline (speedup 1.0000x reference)
#include <cuda_runtime.h>
#include <cuda_bf16.h>
#include <cstdint>

// Problem constants
#define BATCH   1024
#define TWO_B   2048
#define DFLAT   16384          // 128*128
#define TEMP_INV 2.0f          // 1/0.5

// ---------------- scratch (static __device__; no runtime alloc) ----------------
__device__ __nv_bfloat16 g_rn[(size_t)TWO_B * DFLAT];   // 64 MB, fits L2
__device__ float         g_sim[(size_t)TWO_B * TWO_B];  // 16 MB
__device__ float         g_row[TWO_B];

// ---------------- helpers ----------------
__device__ __forceinline__ void cpasync16(void* smem, const void* gmem) {
    uint32_t s = (uint32_t)__cvta_generic_to_shared(smem);
    asm volatile("cp.async.ca.shared.global [%0], [%1], 16;\n" :: "r"(s), "l"(gmem));
}
#define CP_COMMIT() asm volatile("cp.async.commit_group;\n")
#define CP_WAIT(N)  asm volatile("cp.async.wait_group %0;\n" :: "n"(N))

__device__ __forceinline__ void mma16816(float* c, const uint32_t* a, uint32_t b0, uint32_t b1) {
    asm volatile(
        "mma.sync.aligned.m16n8k16.row.col.f32.bf16.bf16.f32 "
        "{%0,%1,%2,%3}, {%4,%5,%6,%7}, {%8,%9}, {%0,%1,%2,%3};\n"
        : "+f"(c[0]), "+f"(c[1]), "+f"(c[2]), "+f"(c[3])
        : "r"(a[0]), "r"(a[1]), "r"(a[2]), "r"(a[3]), "r"(b0), "r"(b1));
}

// ---------------- kernel 1: fused double normalization -> bf16 rn ----------------
// One block per sample b in [0, 2B). 128 threads; thread n owns column n.
__global__ void nrm_kernel(const float* __restrict__ ei, const float* __restrict__ ej) {
    int b = blockIdx.x;
    const float* src = (b < BATCH) ? (ei + (size_t)b * DFLAT)
                                   : (ej + (size_t)(b - BATCH) * DFLAT);
    int n = threadIdx.x;

    float s = 0.f;
    #pragma unroll 8
    for (int m = 0; m < 128; m++) {
        float v = src[m * 128 + n];
        s += v * v;
    }
    // F.normalize(dim=1): x / max(sqrt(s), 1e-12)
    float inv = 1.f / fmaxf(sqrtf(s), 1e-12f);
    // column sum-of-squares after normalization (== 1 unless clamped)
    float c1 = s * inv * inv;

    __shared__ float red[128];
    red[n] = c1;
    __syncthreads();
    for (int off = 64; off > 0; off >>= 1) {
        if (n < off) red[n] += red[n + off];
        __syncthreads();
    }
    float tot = red[0];
    // cosine-similarity renorm: / max(sqrt(tot), 1e-8)
    float finv = 1.f / fmaxf(sqrtf(tot), 1e-8f);
    float scale = inv * finv;

    __nv_bfloat16* dst = g_rn + (size_t)b * DFLAT;
    #pragma unroll 8
    for (int m = 0; m < 128; m++) {
        dst[m * 128 + n] = __float2bfloat16(src[m * 128 + n] * scale);
    }
}

// ---------------- kernel 2: sim = rn @ rn^T  (bf16 mma.sync, fp32 accum) ----------------
// Tile 128x128, BK=32, 256 threads = 8 warps (4 x 2), warp tile 32x64.
#define BK 32
#define KT (DFLAT / BK)   // 512

__device__ __forceinline__ void stage_load(__nv_bfloat16 (&As)[128][40],
                                           __nv_bfloat16 (&Bs)[128][40],
                                           const __nv_bfloat16* gA,
                                           const __nv_bfloat16* gB,
                                           int k0, int tid) {
    #pragma unroll
    for (int it = 0; it < 2; it++) {
        int c   = tid + it * 256;
        int row = c >> 2;
        int ch  = (c & 3) * 8;              // bf16 offset within BK row
        cpasync16(&As[row][ch], gA + (size_t)row * DFLAT + k0 + ch);
        cpasync16(&Bs[row][ch], gB + (size_t)row * DFLAT + k0 + ch);
    }
}

__global__ __launch_bounds__(256, 2) void gemm_kernel() {
    __shared__ __nv_bfloat16 As[2][128][40];   // +8 pad -> conflict-free frag loads
    __shared__ __nv_bfloat16 Bs[2][128][40];

    const int bn = blockIdx.x, bm = blockIdx.y;
    const int tid  = threadIdx.x;
    const int warp = tid >> 5, lane = tid & 31;
    const int wm = warp >> 1;          // 0..3 -> 32 rows each
    const int wn = warp & 1;           // 0..1 -> 64 cols each
    const int g = lane >> 2, tig = lane & 3;

    const __nv_bfloat16* gA = g_rn + (size_t)(bm * 128) * DFLAT;
    const __nv_bfloat16* gB = g_rn + (size_t)(bn * 128) * DFLAT;

    float acc[2][8][4];
    #pragma unroll
    for (int mt = 0; mt < 2; mt++)
        #pragma unroll
        for (int nt = 0; nt < 8; nt++)
            #pragma unroll
            for (int q = 0; q < 4; q++) acc[mt][nt][q] = 0.f;

    stage_load(As[0], Bs[0], gA, gB, 0, tid);
    CP_COMMIT();

    for (int kt = 0; kt < KT; kt++) {
        const int p = kt & 1;
        if (kt + 1 < KT) {
            stage_load(As[p ^ 1], Bs[p ^ 1], gA, gB, (kt + 1) * BK, tid);
            CP_COMMIT();
            CP_WAIT(1);
        } else {
            CP_WAIT(0);
        }
        __syncthreads();

        #pragma unroll
        for (int ks = 0; ks < 2; ks++) {
            uint32_t a[2][4];
            #pragma unroll
            for (int mt = 0; mt < 2; mt++) {
                int r0 = wm * 32 + mt * 16 + g;
                a[mt][0] = *(const uint32_t*)&As[p][r0    ][ks * 16 + tig * 2];
                a[mt][1] = *(const uint32_t*)&As[p][r0 + 8][ks * 16 + tig * 2];
                a[mt][2] = *(const uint32_t*)&As[p][r0    ][ks * 16 + tig * 2 + 8];
                a[mt][3] = *(const uint32_t*)&As[p][r0 + 8][ks * 16 + tig * 2 + 8];
            }
            #pragma unroll
            for (int nt = 0; nt < 8; nt++) {
                int cr = wn * 64 + nt * 8 + g;
                uint32_t b0 = *(const uint32_t*)&Bs[p][cr][ks * 16 + tig * 2];
                uint32_t b1 = *(const uint32_t*)&Bs[p][cr][ks * 16 + tig * 2 + 8];
                mma16816(acc[0][nt], a[0], b0, b1);
                mma16816(acc[1][nt], a[1], b0, b1);
            }
        }
        __syncthreads();
    }

    // epilogue: write fp32 sim tile
    float* base = g_sim + (size_t)(bm * 128) * TWO_B + bn * 128;
    #pragma unroll
    for (int mt = 0; mt < 2; mt++) {
        int r = wm * 32 + mt * 16 + g;
        #pragma unroll
        for (int nt = 0; nt < 8; nt++) {
            int c = wn * 64 + nt * 8 + tig * 2;
            float2 v0 = make_float2(acc[mt][nt][0], acc[mt][nt][1]);
            float2 v1 = make_float2(acc[mt][nt][2], acc[mt][nt][3]);
            *(float2*)&base[(size_t)r * TWO_B + c]       = v0;
            *(float2*)&base[(size_t)(r + 8) * TWO_B + c] = v1;
        }
    }
}

// ---------------- kernel 3: per-row  log(sum_{j!=i} exp(2 s_ij)) - 2*pos_i ----------------
__global__ void row_kernel() {
    int i = blockIdx.x;
    const float* r = g_sim + (size_t)i * TWO_B;
    float s = 0.f;
    for (int j = threadIdx.x; j < TWO_B; j += 256)
        s += __expf(TEMP_INV * r[j]);

    __shared__ float red[256];
    red[threadIdx.x] = s;
    __syncthreads();
    for (int off = 128; off > 0; off >>= 1) {
        if (threadIdx.x < off) red[threadIdx.x] += red[threadIdx.x + off];
        __syncthreads();
    }
    if (threadIdx.x == 0) {
        float total = red[0] - __expf(TEMP_INV * r[i]);        // drop diagonal
        float pos   = r[(i + BATCH) & (TWO_B - 1)];            // sim(i, i±B)
        g_row[i] = logf(total) - TEMP_INV * pos;
    }
}

// ---------------- kernel 4: final scalar ----------------
__global__ void fin_kernel(float* __restrict__ out) {
    float s = 0.f;
    for (int i = threadIdx.x; i < TWO_B; i += 256) s += g_row[i];
    __shared__ float red[256];
    red[threadIdx.x] = s;
    __syncthreads();
    for (int off = 128; off > 0; off >>= 1) {
        if (threadIdx.x < off) red[threadIdx.x] += red[threadIdx.x + off];
        __syncthreads();
    }
    if (threadIdx.x == 0) out[0] = red[0] / (float)TWO_B;
}

// ---------------- launch ----------------
extern "C" void kernel_launch(void* const* d_in, const int* in_sizes, int n_in,
                              void* d_out, int out_size) {
    const float* ei = (const float*)d_in[0];
    const float* ej = (const float*)d_in[1];
    float* out = (float*)d_out;

    nrm_kernel<<<TWO_B, 128>>>(ei, ej);
    gemm_kernel<<<dim3(TWO_B / 128, TWO_B / 128), 256>>>();
    row_kernel<<<TWO_B, 256>>>();
    fin_kernel<<<1, 256>>>(out);
}

// round 3
// speedup vs baseline: 2.1844x; 2.1844x over previous
#include <cuda_runtime.h>
#include <cuda_bf16.h>
#include <cstdint>

#define BATCH   1024
#define TWO_B   2048
#define DFLAT   16384
#define NBLK    16              // 2048/128 row/col blocks

// ---------------- scratch ----------------
__device__ __nv_bfloat16 g_rn[(size_t)TWO_B * DFLAT];   // 64 MB (fits L2)
__device__ float         g_row[TWO_B];                  // masked exp row sums
__device__ float         g_pos[TWO_B];                  // sim(i, i±B)

// ---------------- helpers ----------------
__device__ __forceinline__ uint32_t smem_u32(const void* p) {
    return (uint32_t)__cvta_generic_to_shared(p);
}
__device__ __forceinline__ void cpasync16(uint32_t s, const void* g) {
    asm volatile("cp.async.ca.shared.global [%0], [%1], 16;\n" :: "r"(s), "l"(g));
}
#define CP_COMMIT() asm volatile("cp.async.commit_group;\n")
#define CP_WAIT(N)  asm volatile("cp.async.wait_group %0;\n" :: "n"(N))

#define LDSM4(r0, r1, r2, r3, a) \
    asm volatile("ldmatrix.sync.aligned.m8n8.x4.shared.b16 {%0,%1,%2,%3}, [%4];" \
                 : "=r"(r0), "=r"(r1), "=r"(r2), "=r"(r3) : "r"(a))

__device__ __forceinline__ void mma16816(float* c, const uint32_t* a, uint32_t b0, uint32_t b1) {
    asm volatile(
        "mma.sync.aligned.m16n8k16.row.col.f32.bf16.bf16.f32 "
        "{%0,%1,%2,%3}, {%4,%5,%6,%7}, {%8,%9}, {%0,%1,%2,%3};\n"
        : "+f"(c[0]), "+f"(c[1]), "+f"(c[2]), "+f"(c[3])
        : "r"(a[0]), "r"(a[1]), "r"(a[2]), "r"(a[3]), "r"(b0), "r"(b1));
}

// ---------------- kernel 1: fused double normalization (read-once via smem) ----------------
__global__ void nrm_kernel(const float* __restrict__ ei, const float* __restrict__ ej) {
    extern __shared__ float sbuf[];          // 64 KB: the whole [128,128] sample
    int b = blockIdx.x;
    const float* src = (b < BATCH) ? (ei + (size_t)b * DFLAT)
                                   : (ej + (size_t)(b - BATCH) * DFLAT);
    int n = threadIdx.x;
    if (n == 0) g_row[b] = 0.f;              // zero accumulators for gemm epilogue

    float s = 0.f;
    #pragma unroll 8
    for (int m = 0; m < 128; m++) {
        float v = src[m * 128 + n];
        sbuf[m * 128 + n] = v;
        s += v * v;
    }
    float inv = 1.f / fmaxf(sqrtf(s), 1e-12f);
    float c1 = s * inv * inv;

    __shared__ float red[128];
    red[n] = c1;
    __syncthreads();
    for (int off = 64; off > 0; off >>= 1) {
        if (n < off) red[n] += red[n + off];
        __syncthreads();
    }
    float finv = 1.f / fmaxf(sqrtf(red[0]), 1e-8f);
    float scale = inv * finv;

    __nv_bfloat16* dst = g_rn + (size_t)b * DFLAT;
    #pragma unroll 8
    for (int m = 0; m < 128; m++)
        dst[m * 128 + n] = __float2bfloat16(sbuf[m * 128 + n] * scale);
}

// ---------------- kernel 2: symmetric bf16 GEMM + fused exp/row-reduce epilogue ----------------
// 136 CTAs = upper-triangle 128x128 tiles. BK=64 (one SW128 row), 3-stage cp.async.
// 8 warps, warp tile 32x64 via mma.sync.m16n8k16, ldmatrix fragment loads.
#define BK       64
#define KSTEPS   (DFLAT / BK)          // 256
#define A_BYTES  (128 * 128)           // 16 KB per operand per stage
#define STAGE_B  (2 * A_BYTES)         // 32 KB
#define GSMEM    (3 * STAGE_B)         // 96 KB

__global__ void __launch_bounds__(256, 1) gemm_kernel() {
    extern __shared__ char sm[];
    const uint32_t sbase = smem_u32(sm);
    const int tid = threadIdx.x;
    const int warp = tid >> 5, lane = tid & 31;
    const int wm = warp >> 1, wn = warp & 1;
    const int g = lane >> 2, tig = lane & 3;

    // upper-triangle tile decode
    int t = blockIdx.x, bm = 0;
    while (t >= NBLK - bm) { t -= NBLK - bm; bm++; }
    const int bn = bm + t;
    const bool diag  = (bn == bm);
    const bool ptile = (bn - bm == 8);

    const __nv_bfloat16* gA = g_rn + (size_t)(bm * 128) * DFLAT;
    const __nv_bfloat16* gB = g_rn + (size_t)(bn * 128) * DFLAT;

    float acc[2][8][4];
    #pragma unroll
    for (int mt = 0; mt < 2; mt++)
        #pragma unroll
        for (int nt = 0; nt < 8; nt++)
            #pragma unroll
            for (int q = 0; q < 4; q++) acc[mt][nt][q] = 0.f;

    // ---- stage loader: 2048 x 16B chunks, 8 per thread ----
    auto load_stage = [&](int s, int buf) {
        const uint32_t base = sbase + buf * STAGE_B;
        const int k0 = s * BK;
        #pragma unroll
        for (int i = 0; i < 8; i++) {
            int c = tid + i * 256;
            int cc  = c & 1023;
            int row = cc >> 3;
            int cb  = (cc & 7) * 16;
            uint32_t off = row * 128 + (cb ^ ((row & 7) << 4));
            const __nv_bfloat16* src = (c < 1024 ? gA : gB) + (size_t)row * DFLAT + k0 + (cc & 7) * 8;
            cpasync16(base + (c < 1024 ? 0 : A_BYTES) + off, src);
        }
    };

    load_stage(0, 0); CP_COMMIT();
    load_stage(1, 1); CP_COMMIT();
    load_stage(2, 2); CP_COMMIT();

    // ---- per-lane ldmatrix address constants ----
    const int lrow = lane & 15;
    const int hi   = (lane >> 4) * 16;
    uint32_t aBase[2], aXr[2], bBase[4], bXr[4];
    #pragma unroll
    for (int mt = 0; mt < 2; mt++) {
        int r = wm * 32 + mt * 16 + lrow;
        aBase[mt] = r * 128;  aXr[mt] = (r & 7) << 4;
    }
    #pragma unroll
    for (int p = 0; p < 4; p++) {
        int r = wn * 64 + p * 16 + lrow;
        bBase[p] = A_BYTES + r * 128;  bXr[p] = (r & 7) << 4;
    }

    int buf = 0;
    for (int s = 0; s < KSTEPS; s++) {
        CP_WAIT(2);
        __syncthreads();
        const uint32_t stg = sbase + buf * STAGE_B;

        #pragma unroll
        for (int ks = 0; ks < 4; ks++) {
            const int kb = ks * 32 + hi;
            uint32_t a0[4], a1[4], bb[4][4];
            LDSM4(a0[0], a0[1], a0[2], a0[3], stg + aBase[0] + (kb ^ aXr[0]));
            LDSM4(a1[0], a1[1], a1[2], a1[3], stg + aBase[1] + (kb ^ aXr[1]));
            #pragma unroll
            for (int p = 0; p < 4; p++)
                LDSM4(bb[p][0], bb[p][1], bb[p][2], bb[p][3], stg + bBase[p] + (kb ^ bXr[p]));
            #pragma unroll
            for (int nt = 0; nt < 8; nt++) {
                uint32_t b0 = bb[nt >> 1][nt & 1];
                uint32_t b1 = bb[nt >> 1][(nt & 1) + 2];
                mma16816(acc[0][nt], a0, b0, b1);
                mma16816(acc[1][nt], a1, b0, b1);
            }
        }
        __syncthreads();
        if (s + 3 < KSTEPS) load_stage(s + 3, buf);
        CP_COMMIT();                       // empty groups in tail keep counts aligned
        buf = (buf == 2) ? 0 : buf + 1;
    }

    // ---- fused epilogue: e = exp(2v); rows (direct) + cols (= transpose rows) ----
    float rowp[2][2] = {{0.f, 0.f}, {0.f, 0.f}};
    float colp[8][2];
    #pragma unroll
    for (int nt = 0; nt < 8; nt++) colp[nt][0] = colp[nt][1] = 0.f;

    #pragma unroll
    for (int mt = 0; mt < 2; mt++) {
        const int rl = wm * 32 + mt * 16 + g;     // local rows rl, rl+8
        #pragma unroll
        for (int nt = 0; nt < 8; nt++) {
            const int cl = wn * 64 + nt * 8 + tig * 2;   // local cols cl, cl+1
            float v0 = acc[mt][nt][0], v1 = acc[mt][nt][1];
            float v2 = acc[mt][nt][2], v3 = acc[mt][nt][3];
            float e0 = __expf(2.f * v0), e1 = __expf(2.f * v1);
            float e2 = __expf(2.f * v2), e3 = __expf(2.f * v3);
            if (diag) {                      // drop exact diagonal
                if (rl == cl)         e0 = 0.f;
                if (rl == cl + 1)     e1 = 0.f;
                if (rl + 8 == cl)     e2 = 0.f;
                if (rl + 8 == cl + 1) e3 = 0.f;
            }
            if (ptile) {                     // capture positives sim(i, i+B)
                int gr = bm * 128 + rl;
                if (rl == cl)         { g_pos[gr]     = v0; g_pos[gr + BATCH]     = v0; }
                if (rl == cl + 1)     { g_pos[gr]     = v1; g_pos[gr + BATCH]     = v1; }
                if (rl + 8 == cl)     { g_pos[gr + 8] = v2; g_pos[gr + 8 + BATCH] = v2; }
                if (rl + 8 == cl + 1) { g_pos[gr + 8] = v3; g_pos[gr + 8 + BATCH] = v3; }
            }
            rowp[mt][0] += e0 + e1;
            rowp[mt][1] += e2 + e3;
            colp[nt][0] += e0 + e2;
            colp[nt][1] += e1 + e3;
        }
    }

    // row partials: reduce over tig lanes (same g, different cols)
    #pragma unroll
    for (int mt = 0; mt < 2; mt++)
        #pragma unroll
        for (int h = 0; h < 2; h++) {
            float v = rowp[mt][h];
            v += __shfl_xor_sync(0xFFFFFFFF, v, 1);
            v += __shfl_xor_sync(0xFFFFFFFF, v, 2);
            if (tig == 0)
                atomicAdd(&g_row[bm * 128 + wm * 32 + mt * 16 + g + h * 8], v);
        }

    // col partials = transpose-row sums: reduce over g lanes (skip on diagonal tiles)
    if (!diag) {
        #pragma unroll
        for (int nt = 0; nt < 8; nt++)
            #pragma unroll
            for (int q = 0; q < 2; q++) {
                float v = colp[nt][q];
                v += __shfl_xor_sync(0xFFFFFFFF, v, 4);
                v += __shfl_xor_sync(0xFFFFFFFF, v, 8);
                v += __shfl_xor_sync(0xFFFFFFFF, v, 16);
                if (g == 0)
                    atomicAdd(&g_row[bn * 128 + wn * 64 + nt * 8 + tig * 2 + q], v);
            }
    }
}

// ---------------- kernel 3: final scalar ----------------
__global__ void fin_kernel(float* __restrict__ out) {
    float s = 0.f;
    for (int i = threadIdx.x; i < TWO_B; i += 256)
        s += logf(g_row[i]) - 2.f * g_pos[i];
    __shared__ float red[256];
    red[threadIdx.x] = s;
    __syncthreads();
    for (int off = 128; off > 0; off >>= 1) {
        if (threadIdx.x < off) red[threadIdx.x] += red[threadIdx.x + off];
        __syncthreads();
    }
    if (threadIdx.x == 0) out[0] = red[0] / (float)TWO_B;
}

// ---------------- launch ----------------
extern "C" void kernel_launch(void* const* d_in, const int* in_sizes, int n_in,
                              void* d_out, int out_size) {
    const float* ei = (const float*)d_in[0];
    const float* ej = (const float*)d_in[1];
    float* out = (float*)d_out;

    cudaFuncSetAttribute(nrm_kernel,  cudaFuncAttributeMaxDynamicSharedMemorySize, 65536);
    cudaFuncSetAttribute(gemm_kernel, cudaFuncAttributeMaxDynamicSharedMemorySize, GSMEM);

    nrm_kernel<<<TWO_B, 128, 65536>>>(ei, ej);
    gemm_kernel<<<136, 256, GSMEM>>>();
    fin_kernel<<<1, 256>>>(out);
}

// round 4
// speedup vs baseline: 2.3759x; 1.0877x over previous
#include <cuda_runtime.h>
#include <cuda_bf16.h>
#include <cstdint>

#define BATCH   1024
#define TWO_B   2048
#define DFLAT   16384
#define NBLK    16              // 2048/128 tile blocks
#define FP8_SCALE 128.f
#define INV_ACC   (1.f / 16384.f)   // undo FP8_SCALE^2

// ---------------- scratch ----------------
__device__ uint8_t g_rn[(size_t)TWO_B * DFLAT];   // 32 MB e4m3 (L2-resident)
__device__ float   g_row[TWO_B];                  // masked exp row sums
__device__ float   g_pos[TWO_B];                  // sim(i, i±B)

// ---------------- helpers ----------------
__device__ __forceinline__ uint32_t smem_u32(const void* p) {
    return (uint32_t)__cvta_generic_to_shared(p);
}
__device__ __forceinline__ void cpasync16(uint32_t s, const void* g) {
    asm volatile("cp.async.ca.shared.global [%0], [%1], 16;\n" :: "r"(s), "l"(g));
}
#define CP_COMMIT() asm volatile("cp.async.commit_group;\n")
#define CP_WAIT(N)  asm volatile("cp.async.wait_group %0;\n" :: "n"(N))

#define LDSM4(r0, r1, r2, r3, a) \
    asm volatile("ldmatrix.sync.aligned.m8n8.x4.shared.b16 {%0,%1,%2,%3}, [%4];" \
                 : "=r"(r0), "=r"(r1), "=r"(r2), "=r"(r3) : "r"(a))

// fp8 e4m3 mma, fp32 accum: same fragment geometry as bf16 k16 (1 b16 = 2 fp8)
__device__ __forceinline__ void mma16832(float* c, const uint32_t* a, uint32_t b0, uint32_t b1) {
    asm volatile(
        "mma.sync.aligned.m16n8k32.row.col.f32.e4m3.e4m3.f32 "
        "{%0,%1,%2,%3}, {%4,%5,%6,%7}, {%8,%9}, {%0,%1,%2,%3};\n"
        : "+f"(c[0]), "+f"(c[1]), "+f"(c[2]), "+f"(c[3])
        : "r"(a[0]), "r"(a[1]), "r"(a[2]), "r"(a[3]), "r"(b0), "r"(b1));
}

// pack 2 floats -> 2 e4m3 bytes: result[15:8]=cvt(hi), [7:0]=cvt(lo)
__device__ __forceinline__ uint32_t f2_e4m3x2(float hi, float lo) {
    uint16_t r;
    asm volatile("cvt.rn.satfinite.e4m3x2.f32 %0, %1, %2;" : "=h"(r) : "f"(hi), "f"(lo));
    return (uint32_t)r;
}

// ---------------- kernel 1: fused double normalization -> scaled e4m3 ----------------
// One block per sample. 128 threads = 4 warps; thread owns 4 adjacent columns
// (float4) over its warp's 32 rows.
__global__ void __launch_bounds__(128) nrm_kernel(const float* __restrict__ ei,
                                                  const float* __restrict__ ej) {
    const int b = blockIdx.x;
    const float* src = (b < BATCH) ? (ei + (size_t)b * DFLAT)
                                   : (ej + (size_t)(b - BATCH) * DFLAT);
    const int tid = threadIdx.x;
    const int w = tid >> 5, lane = tid & 31;
    const int c4 = lane * 4;          // first of 4 columns
    const int r0 = w * 32;            // first of 32 rows
    if (tid == 0) g_row[b] = 0.f;

    // pass 1: per-column sum of squares (partial over 32 rows)
    float4 s4 = make_float4(0.f, 0.f, 0.f, 0.f);
    #pragma unroll 8
    for (int r = 0; r < 32; r++) {
        float4 v = *(const float4*)&src[(r0 + r) * 128 + c4];
        s4.x += v.x * v.x; s4.y += v.y * v.y;
        s4.z += v.z * v.z; s4.w += v.w * v.w;
    }
    __shared__ float4 sred[4][32];
    sred[w][lane] = s4;
    __syncthreads();
    float4 cs;
    {
        float4 a = sred[0][lane], bb = sred[1][lane], c = sred[2][lane], d = sred[3][lane];
        cs = make_float4(a.x + bb.x + c.x + d.x, a.y + bb.y + c.y + d.y,
                         a.z + bb.z + c.z + d.z, a.w + bb.w + c.w + d.w);
    }
    float4 inv = make_float4(1.f / fmaxf(sqrtf(cs.x), 1e-12f),
                             1.f / fmaxf(sqrtf(cs.y), 1e-12f),
                             1.f / fmaxf(sqrtf(cs.z), 1e-12f),
                             1.f / fmaxf(sqrtf(cs.w), 1e-12f));
    // flat-vector norm^2 after dim-1 normalization
    float t = cs.x * inv.x * inv.x + cs.y * inv.y * inv.y
            + cs.z * inv.z * inv.z + cs.w * inv.w * inv.w;
    #pragma unroll
    for (int off = 16; off > 0; off >>= 1) t += __shfl_xor_sync(0xFFFFFFFF, t, off);
    const float finv = 1.f / fmaxf(sqrtf(t), 1e-8f);
    const float4 scl = make_float4(inv.x * finv * FP8_SCALE, inv.y * finv * FP8_SCALE,
                                   inv.z * finv * FP8_SCALE, inv.w * finv * FP8_SCALE);

    // pass 2: re-read (L2-hot), scale, quantize, 4B store
    uint32_t* dst = (uint32_t*)(g_rn + (size_t)b * DFLAT);
    #pragma unroll 4
    for (int r = 0; r < 32; r++) {
        float4 v = *(const float4*)&src[(r0 + r) * 128 + c4];
        uint32_t lo = f2_e4m3x2(v.y * scl.y, v.x * scl.x);
        uint32_t hi = f2_e4m3x2(v.w * scl.w, v.z * scl.z);
        dst[((r0 + r) * 128 + c4) >> 2] = (hi << 16) | lo;
    }
}

// ---------------- kernel 2: symmetric FP8 GEMM + fused exp/row-reduce epilogue ----------------
// 136 CTAs = upper-triangle 128x128 tiles. BK=128 fp8 bytes (one SW128 row),
// 3-stage cp.async, 8 warps, warp tile 32x64, mma.m16n8k32.
#define BK       128
#define KSTEPS   (DFLAT / BK)          // 128
#define A_BYTES  (128 * 128)           // 16 KB per operand per stage
#define STAGE_B  (2 * A_BYTES)         // 32 KB
#define GSMEM    (3 * STAGE_B)         // 96 KB

__global__ void __launch_bounds__(256, 1) gemm_kernel() {
    extern __shared__ char sm[];
    const uint32_t sbase = smem_u32(sm);
    const int tid = threadIdx.x;
    const int warp = tid >> 5, lane = tid & 31;
    const int wm = warp >> 1, wn = warp & 1;
    const int g = lane >> 2, tig = lane & 3;

    // upper-triangle tile decode
    int t = blockIdx.x, bm = 0;
    while (t >= NBLK - bm) { t -= NBLK - bm; bm++; }
    const int bn = bm + t;
    const bool diag  = (bn == bm);
    const bool ptile = (bn - bm == 8);

    const uint8_t* gA = g_rn + (size_t)(bm * 128) * DFLAT;
    const uint8_t* gB = g_rn + (size_t)(bn * 128) * DFLAT;

    float acc[2][8][4];
    #pragma unroll
    for (int mt = 0; mt < 2; mt++)
        #pragma unroll
        for (int nt = 0; nt < 8; nt++)
            #pragma unroll
            for (int q = 0; q < 4; q++) acc[mt][nt][q] = 0.f;

    // stage loader: 2048 x 16B chunks, 8 per thread
    auto load_stage = [&](int s, int buf) {
        const uint32_t base = sbase + buf * STAGE_B;
        const int k0 = s * BK;
        #pragma unroll
        for (int i = 0; i < 8; i++) {
            int c = tid + i * 256;
            int cc  = c & 1023;
            int row = cc >> 3;
            int cb  = (cc & 7) * 16;
            uint32_t off = row * 128 + (cb ^ ((row & 7) << 4));
            const uint8_t* src = (c < 1024 ? gA : gB) + (size_t)row * DFLAT + k0 + cb;
            cpasync16(base + (c < 1024 ? 0 : A_BYTES) + off, src);
        }
    };

    load_stage(0, 0); CP_COMMIT();
    load_stage(1, 1); CP_COMMIT();
    load_stage(2, 2); CP_COMMIT();

    // ldmatrix per-lane address constants (byte offsets)
    const int lrow = lane & 15;
    const int hi   = (lane >> 4) * 16;
    uint32_t aBase[2], aXr[2], bBase[4], bXr[4];
    #pragma unroll
    for (int mt = 0; mt < 2; mt++) {
        int r = wm * 32 + mt * 16 + lrow;
        aBase[mt] = r * 128;  aXr[mt] = (r & 7) << 4;
    }
    #pragma unroll
    for (int p = 0; p < 4; p++) {
        int r = wn * 64 + p * 16 + lrow;
        bBase[p] = A_BYTES + r * 128;  bXr[p] = (r & 7) << 4;
    }

    int buf = 0;
    for (int s = 0; s < KSTEPS; s++) {
        CP_WAIT(2);
        __syncthreads();
        const uint32_t stg = sbase + buf * STAGE_B;

        #pragma unroll
        for (int ks = 0; ks < 4; ks++) {        // 32 fp8 bytes per ks
            const int kb = ks * 32 + hi;
            uint32_t a0[4], a1[4], bb[4][4];
            LDSM4(a0[0], a0[1], a0[2], a0[3], stg + aBase[0] + (kb ^ aXr[0]));
            LDSM4(a1[0], a1[1], a1[2], a1[3], stg + aBase[1] + (kb ^ aXr[1]));
            #pragma unroll
            for (int p = 0; p < 4; p++)
                LDSM4(bb[p][0], bb[p][1], bb[p][2], bb[p][3], stg + bBase[p] + (kb ^ bXr[p]));
            #pragma unroll
            for (int nt = 0; nt < 8; nt++) {
                uint32_t b0 = bb[nt >> 1][nt & 1];
                uint32_t b1 = bb[nt >> 1][(nt & 1) + 2];
                mma16832(acc[0][nt], a0, b0, b1);
                mma16832(acc[1][nt], a1, b0, b1);
            }
        }
        __syncthreads();
        if (s + 3 < KSTEPS) load_stage(s + 3, buf);
        CP_COMMIT();                        // empty tail groups keep counts aligned
        buf = (buf == 2) ? 0 : buf + 1;
    }

    // fused epilogue: v = acc/16384; e = exp(2v); rows direct + cols (transpose rows)
    float rowp[2][2] = {{0.f, 0.f}, {0.f, 0.f}};
    float colp[8][2];
    #pragma unroll
    for (int nt = 0; nt < 8; nt++) colp[nt][0] = colp[nt][1] = 0.f;

    #pragma unroll
    for (int mt = 0; mt < 2; mt++) {
        const int rl = wm * 32 + mt * 16 + g;
        #pragma unroll
        for (int nt = 0; nt < 8; nt++) {
            const int cl = wn * 64 + nt * 8 + tig * 2;
            float v0 = acc[mt][nt][0] * INV_ACC, v1 = acc[mt][nt][1] * INV_ACC;
            float v2 = acc[mt][nt][2] * INV_ACC, v3 = acc[mt][nt][3] * INV_ACC;
            float e0 = __expf(2.f * v0), e1 = __expf(2.f * v1);
            float e2 = __expf(2.f * v2), e3 = __expf(2.f * v3);
            if (diag) {
                if (rl == cl)         e0 = 0.f;
                if (rl == cl + 1)     e1 = 0.f;
                if (rl + 8 == cl)     e2 = 0.f;
                if (rl + 8 == cl + 1) e3 = 0.f;
            }
            if (ptile) {
                int gr = bm * 128 + rl;
                if (rl == cl)         { g_pos[gr]     = v0; g_pos[gr + BATCH]     = v0; }
                if (rl == cl + 1)     { g_pos[gr]     = v1; g_pos[gr + BATCH]     = v1; }
                if (rl + 8 == cl)     { g_pos[gr + 8] = v2; g_pos[gr + 8 + BATCH] = v2; }
                if (rl + 8 == cl + 1) { g_pos[gr + 8] = v3; g_pos[gr + 8 + BATCH] = v3; }
            }
            rowp[mt][0] += e0 + e1;
            rowp[mt][1] += e2 + e3;
            colp[nt][0] += e0 + e2;
            colp[nt][1] += e1 + e3;
        }
    }

    #pragma unroll
    for (int mt = 0; mt < 2; mt++)
        #pragma unroll
        for (int h = 0; h < 2; h++) {
            float v = rowp[mt][h];
            v += __shfl_xor_sync(0xFFFFFFFF, v, 1);
            v += __shfl_xor_sync(0xFFFFFFFF, v, 2);
            if (tig == 0)
                atomicAdd(&g_row[bm * 128 + wm * 32 + mt * 16 + g + h * 8], v);
        }

    if (!diag) {
        #pragma unroll
        for (int nt = 0; nt < 8; nt++)
            #pragma unroll
            for (int q = 0; q < 2; q++) {
                float v = colp[nt][q];
                v += __shfl_xor_sync(0xFFFFFFFF, v, 4);
                v += __shfl_xor_sync(0xFFFFFFFF, v, 8);
                v += __shfl_xor_sync(0xFFFFFFFF, v, 16);
                if (g == 0)
                    atomicAdd(&g_row[bn * 128 + wn * 64 + nt * 8 + tig * 2 + q], v);
            }
    }
}

// ---------------- kernel 3: final scalar ----------------
__global__ void fin_kernel(float* __restrict__ out) {
    float s = 0.f;
    for (int i = threadIdx.x; i < TWO_B; i += 256)
        s += logf(g_row[i]) - 2.f * g_pos[i];
    __shared__ float red[256];
    red[threadIdx.x] = s;
    __syncthreads();
    for (int off = 128; off > 0; off >>= 1) {
        if (threadIdx.x < off) red[threadIdx.x] += red[threadIdx.x + off];
        __syncthreads();
    }
    if (threadIdx.x == 0) out[0] = red[0] / (float)TWO_B;
}

// ---------------- launch ----------------
extern "C" void kernel_launch(void* const* d_in, const int* in_sizes, int n_in,
                              void* d_out, int out_size) {
    const float* ei = (const float*)d_in[0];
    const float* ej = (const float*)d_in[1];
    float* out = (float*)d_out;

    cudaFuncSetAttribute(gemm_kernel, cudaFuncAttributeMaxDynamicSharedMemorySize, GSMEM);

    nrm_kernel<<<TWO_B, 128>>>(ei, ej);
    gemm_kernel<<<136, 256, GSMEM>>>();
    fin_kernel<<<1, 256>>>(out);
}